// round 15
// baseline (speedup 1.0000x reference)
#include <cuda_runtime.h>

#define V0 32768
#define V1 262144
#define V2 2097152
#define OFF_CLS1 32768
#define OFF_CLS2 294912
#define OFF_OUT  2392064
#define NF4 8986624
#define GSB 128
#define GST 256
#define W0PAD 14688  // conv0: 27*544 floats
#define WCPAD 7344   // conv16: 27*272 floats (4 q-chunks of 64+4 pad)
#define WUPAD 2080   // up: 8*260 floats

__device__ float g_feat0[V0 * 16];
__device__ float g_h1[V1 * 16];
__device__ float g_feat1[V1 * 16];
__device__ float g_h2[V2 * 16];
__device__ unsigned char g_occ0[V0], g_gt0[V0], g_gt1[V1], g_gt2[V2];
__device__ unsigned char g_occ1[V1], g_occ2[V2];
__device__ int g_list0[V0], g_list1[V1], g_list2[V2];
__device__ unsigned long long g_keys[V2];
__device__ unsigned int g_hist2[8][256];
__device__ int g_bsum[GSB];
__device__ unsigned int g_syncbar[8];
__device__ int g_mode, g_karr[3], g_ncand;

__device__ __forceinline__ unsigned long long make_key(float f, int idx) {
    unsigned int u = __float_as_uint(f);
    unsigned int m = (u & 0x80000000u) ? ~u : (u | 0x80000000u);
    return ((unsigned long long)m << 32) | (unsigned int)(~(unsigned int)idx);
}

__device__ __forceinline__ float4 fma4(float a, float4 w, float4 c) {
    c.x = fmaf(a, w.x, c.x); c.y = fmaf(a, w.y, c.y);
    c.z = fmaf(a, w.z, c.z); c.w = fmaf(a, w.w, c.w);
    return c;
}

__device__ __forceinline__ float comp4(float4 v, int j) {
    return j == 0 ? v.x : (j == 1 ? v.y : (j == 2 ? v.z : v.w));
}

// ---- packed f32x2 helpers ----
__device__ __forceinline__ unsigned long long pack2s(float a) {
    unsigned long long r;
    asm("mov.b64 %0, {%1, %1};" : "=l"(r) : "f"(a));
    return r;
}
__device__ __forceinline__ unsigned long long pack2(float lo, float hi) {
    unsigned long long r;
    asm("mov.b64 %0, {%1, %2};" : "=l"(r) : "f"(lo), "f"(hi));
    return r;
}
__device__ __forceinline__ void fma2(unsigned long long& c, unsigned long long a,
                                     unsigned long long w) {
    asm("fma.rn.f32x2 %0, %1, %2, %0;" : "+l"(c) : "l"(a), "l"(w));
}
__device__ __forceinline__ float2 unpack2(unsigned long long v) {
    float lo, hi;
    asm("mov.b64 {%0, %1}, %2;" : "=f"(lo), "=f"(hi) : "l"(v));
    return make_float2(lo, hi);
}

__device__ __forceinline__ void oreduce(float4& v) {
#pragma unroll
    for (int d = 1; d <= 4; d <<= 1) {
        v.x += __shfl_xor_sync(0xffffffffu, v.x, d);
        v.y += __shfl_xor_sync(0xffffffffu, v.y, d);
        v.z += __shfl_xor_sync(0xffffffffu, v.z, d);
        v.w += __shfl_xor_sync(0xffffffffu, v.w, d);
    }
}

__device__ __forceinline__ void gsync(int slot, int* cnt) {
    __syncthreads();
    if (threadIdx.x == 0) {
        (*cnt)++;
        __threadfence();
        atomicAdd(&g_syncbar[slot], 1u);
        unsigned int target = (unsigned int)(*cnt) * GSB;
        while (*(volatile unsigned int*)&g_syncbar[slot] < target) { }
        __threadfence();
    }
    __syncthreads();
}

__global__ void k_zero_out(float4* __restrict__ out) {
    int stride = gridDim.x * blockDim.x;
    for (int i = blockIdx.x * blockDim.x + threadIdx.x; i < NF4; i += stride)
        out[i] = make_float4(0.f, 0.f, 0.f, 0.f);
}

__global__ void k_detect(const unsigned char* __restrict__ occ0b,
                         const int* __restrict__ k0p, const int* __restrict__ k1p,
                         const int* __restrict__ k2p) {
    __shared__ int s_not01, s_off4;
    if (threadIdx.x == 0) { s_not01 = 0; s_off4 = 0; }
    __syncthreads();
    for (int i = threadIdx.x; i < 32768; i += 256) {
        unsigned char c = occ0b[i];
        if (c > 1) s_not01 = 1;
        else if (c == 1 && (i & 3)) s_off4 = 1;
    }
    if (threadIdx.x < 8) g_syncbar[threadIdx.x] = 0u;
    __syncthreads();
    if (threadIdx.x == 0) {
        g_mode = s_not01 ? 2 : (s_off4 ? 0 : 1);
        int w;
        w = k0p[0]; g_karr[0] = (w > 0 && w < (1 << 26)) ? w : 8192;
        w = k1p[0]; g_karr[1] = (w > 0 && w < (1 << 26)) ? w : 32768;
        w = k2p[0]; g_karr[2] = (w > 0 && w < (1 << 26)) ? w : 131072;
    }
}

__global__ void k_cvt(const void* __restrict__ occ0p, const void* __restrict__ gt0p,
                      const void* __restrict__ gt1p, const void* __restrict__ gt2p) {
    int mode = g_mode;
    int stride = gridDim.x * blockDim.x;
    for (int i = blockIdx.x * blockDim.x + threadIdx.x; i < 2 * V0 + V1 + V2; i += stride) {
        const void* src; unsigned char* dst; int li;
        if (i < V0)                 { src = occ0p; dst = g_occ0; li = i; }
        else if (i < 2 * V0)        { src = gt0p;  dst = g_gt0;  li = i - V0; }
        else if (i < 2 * V0 + V1)   { src = gt1p;  dst = g_gt1;  li = i - 2 * V0; }
        else                        { src = gt2p;  dst = g_gt2;  li = i - 2 * V0 - V1; }
        unsigned char v;
        if (mode == 0)      v = ((const unsigned char*)src)[li] != 0;
        else if (mode == 1) v = ((const int*)src)[li] != 0;
        else                v = ((const float*)src)[li] != 0.0f;
        dst[li] = v;
    }
}

// fused count + redundant prefix + ordered write (ONE gsync)
__global__ __launch_bounds__(GST) void k_compact(const unsigned char* __restrict__ occ,
                                                 int* __restrict__ list, int N, int slot) {
    int sc = 0;
    int chunk = N / GSB;
    int base = blockIdx.x * chunk;
    int t = threadIdx.x;
    __shared__ int s[GST];
    int sum = 0;
    for (int i = t; i < chunk; i += GST) sum += occ[base + i] ? 1 : 0;
    s[t] = sum;
    __syncthreads();
    for (int off = GST / 2; off > 0; off >>= 1) {
        if (t < off) s[t] += s[t + off];
        __syncthreads();
    }
    if (t == 0) *(volatile int*)&g_bsum[blockIdx.x] = s[0];
    gsync(slot, &sc);
    __shared__ unsigned int ps[GSB];
    if (t < GSB) ps[t] = (unsigned int)(*(volatile int*)&g_bsum[t]);
    __syncthreads();
    for (int off = 1; off < GSB; off <<= 1) {
        unsigned int v = (t < GSB && t >= off) ? ps[t - off] : 0u;
        __syncthreads();
        if (t < GSB) ps[t] += v;
        __syncthreads();
    }
    if (blockIdx.x == 0 && t == 0) g_ncand = (int)ps[GSB - 1];
    __shared__ int s_base;
    __shared__ int warpcnt[GST / 32];
    if (t == 0) s_base = (blockIdx.x == 0) ? 0 : (int)ps[blockIdx.x - 1];
    __syncthreads();
    int wid = t >> 5, lane = t & 31;
    for (int off = 0; off < chunk; off += GST) {
        int j = off + t;
        int v = (j < chunk) ? (occ[base + j] ? 1 : 0) : 0;
        unsigned int bal = __ballot_sync(0xffffffffu, v);
        if (lane == 0) warpcnt[wid] = __popc(bal);
        __syncthreads();
        int wbase = s_base;
        for (int w = 0; w < wid; w++) wbase += warpcnt[w];
        if (v) list[wbase + __popc(bal & ((1u << lane) - 1u))] = base + j;
        __syncthreads();
        if (t == 0) {
            int tot = 0;
            for (int w = 0; w < GST / 32; w++) tot += warpcnt[w];
            s_base += tot;
        }
        __syncthreads();
    }
}

// fused radix select: ONE gsync per pass, redundant scan in every block
__global__ __launch_bounds__(GST) void k_select(const int* __restrict__ list,
                                                const unsigned char* __restrict__ gt,
                                                float* __restrict__ outfeat,
                                                unsigned char* __restrict__ occn,
                                                int level, int sb, int slot) {
    int sc = 0;
    int n = g_ncand;
    int t = threadIdx.x;
    int gtid = blockIdx.x * GST + t;
    int gstride = GSB * GST;
    __shared__ unsigned int sh[256], ss[256];
    __shared__ unsigned int s_krem;
    __shared__ int s_all, s_done;
    __shared__ unsigned long long s_pre;
    if (t == 0) { s_all = 0; s_done = 0; s_pre = 0ULL; s_krem = 0u; }
    __syncthreads();
    int all = 0, done = 0;
    unsigned int krem = 0;
    unsigned long long pre = 0ULL;
    for (int pass = 0; pass < 8; pass++) {
        int shift = 56 - 8 * pass;
        if (!all) {
            sh[t] = 0u;
            __syncthreads();
            for (int i = gtid; i < n; i += gstride) {
                unsigned long long key = g_keys[i];
                if (pass > 0 && ((key ^ pre) >> (shift + 8))) continue;
                atomicAdd(&sh[(unsigned int)(key >> shift) & 255u], 1u);
            }
            __syncthreads();
            if (sh[t]) atomicAdd(&g_hist2[pass][t], sh[t]);
        }
        gsync(slot, &sc);
        unsigned int cnt = g_hist2[pass][t];
        ss[t] = cnt;
        __syncthreads();
        for (int off = 1; off < 256; off <<= 1) {
            unsigned int v = (t + off < 256) ? ss[t + off] : 0u;
            __syncthreads();
            ss[t] += v;
            __syncthreads();
        }
        if (pass == 0) {
            if (t == 0) {
                s_krem = (unsigned int)g_karr[level];
                if (ss[0] <= s_krem) { s_all = 1; s_done = 1; }
            }
            __syncthreads();
            all = s_all; done = s_done; krem = s_krem;
        }
        if (!all) {
            unsigned int kr = krem;
            if (ss[t] >= kr && (t == 255 || ss[t + 1] < kr)) {
                unsigned int above = (t < 255) ? ss[t + 1] : 0u;
                unsigned int krn = kr - above;
                s_pre = pre | ((unsigned long long)t << shift);
                s_krem = krn;
                if (cnt == krn) s_done = 1;
            }
            __syncthreads();
            pre = s_pre; krem = s_krem; done = s_done;
            __syncthreads();
        }
        if (done) break;
    }
    unsigned long long thr = pre;
    int M = (1 << sb) - 1, sbc = sb + 1;
    for (int i = gtid; i < n; i += gstride) {
        int idx = list[i];
        bool m = all || (g_keys[i] >= thr) || gt[idx];
        if (level < 2) {
            if (m) {
                int z = idx >> (2 * sb), y = (idx >> sb) & M, x = idx & M;
                int zb = z << 1, yb = y << 1, xb = x << 1;
#pragma unroll
                for (int dz = 0; dz < 2; dz++)
#pragma unroll
                    for (int dy = 0; dy < 2; dy++) {
                        int o = ((((zb + dz) << sbc) + (yb + dy)) << sbc) + xb;
                        *(unsigned short*)(occn + o) = 0x0101;
                    }
            }
        } else if (!m) {
            float4* p = (float4*)(outfeat + (size_t)idx * 16);
            float4 Z = make_float4(0.f, 0.f, 0.f, 0.f);
            p[0] = Z; p[1] = Z; p[2] = Z; p[3] = Z;
        }
    }
}

// conv0: 32 -> 16, S=32, relu; 8 lanes/voxel; padded smem weights
__global__ __launch_bounds__(256) void k_conv0(const float* __restrict__ x,
                                               const float* __restrict__ w,
                                               const float* __restrict__ b) {
    extern __shared__ float swc[];
    for (int i = threadIdx.x; i < W0PAD; i += 256) {
        int t = i / 544, r = i % 544;
        int sub = r / 68, rr = r % 68;
        swc[i] = (rr < 64) ? w[t * 512 + sub * 64 + rr] : 0.f;
    }
    __syncthreads();
    int n = g_ncand;
    int lane = threadIdx.x & 31;
    int sub = lane & 7;
    int grp = lane >> 3;
    int gw = (blockIdx.x * blockDim.x + threadIdx.x) >> 5;
    int wstride = (gridDim.x * blockDim.x) >> 5;
    const float4 Z = make_float4(0.f, 0.f, 0.f, 0.f);
    for (int base = gw * 4; base < n; base += wstride * 4) {
        int v = base + grp;
        bool live = v < n;
        int idx = g_list0[live ? v : (n - 1)];
        int z = idx >> 10, y = (idx >> 5) & 31, xx = idx & 31;
        float4 acc[4] = {Z, Z, Z, Z};
#pragma unroll 1
        for (int t = 0; t < 27; t++) {
            int dz = t / 9 - 1, dy = (t / 3) % 3 - 1, dx = t % 3 - 1;
            int zz = z + dz, yy = y + dy, xc = xx + dx;
            if ((unsigned)zz >= 32u || (unsigned)yy >= 32u || (unsigned)xc >= 32u) continue;
            const float4* ip4 = (const float4*)(x + ((((zz << 5) + yy) << 5) + xc) * 32);
            float4 A = __ldg(ip4 + sub);
            const float4* wp4 = (const float4*)(swc + t * 544 + sub * 68);
#pragma unroll
            for (int cc = 0; cc < 4; cc++) {
                float a = comp4(A, cc);
                const float4* wr = wp4 + cc * 4;
                acc[0] = fma4(a, wr[0], acc[0]);
                acc[1] = fma4(a, wr[1], acc[1]);
                acc[2] = fma4(a, wr[2], acc[2]);
                acc[3] = fma4(a, wr[3], acc[3]);
            }
        }
        oreduce(acc[0]); oreduce(acc[1]); oreduce(acc[2]); oreduce(acc[3]);
        if (live && sub < 4) {
            float4 bb = __ldg((const float4*)b + sub);
            float4 av = acc[sub];
            float4 r = make_float4(fmaxf(av.x + bb.x, 0.f), fmaxf(av.y + bb.y, 0.f),
                                   fmaxf(av.z + bb.z, 0.f), fmaxf(av.w + bb.w, 0.f));
            ((float4*)(g_feat0 + idx * 16))[sub] = r;
        }
    }
}

// 16->16 conv3x3, relu, QUAD REMAP (4 lanes/voxel, padded weights, no ballots)
__global__ __launch_bounds__(256) void k_conv16(const float* __restrict__ in,
                                                const float* __restrict__ w,
                                                const float* __restrict__ b,
                                                float* __restrict__ out,
                                                const int* __restrict__ list, int S, int sb) {
    __shared__ float sw[WCPAD];  // sw[t*272 + q*68 + j*16 + oc]
    for (int i = threadIdx.x; i < WCPAD; i += blockDim.x) {
        int t = i / 272, r = i % 272;
        int q = r / 68, rr = r % 68;
        sw[i] = (rr < 64) ? w[t * 256 + q * 64 + rr] : 0.f;
    }
    __syncthreads();
    int n = g_ncand;
    int lane = threadIdx.x & 31;
    int q = lane & 3;
    int sub = lane >> 2;
    int wgv = (blockIdx.x * blockDim.x + threadIdx.x) >> 5;
    int wstride = (gridDim.x * blockDim.x) >> 5;
    int M = S - 1;
    const float4 Z = make_float4(0.f, 0.f, 0.f, 0.f);
    for (int base = wgv * 8; base < n; base += wstride * 8) {
        int i = base + sub;
        bool live = i < n;
        int idx = list[live ? i : (n - 1)];
        int z = idx >> (2 * sb), y = (idx >> sb) & M, x = idx & M;
        unsigned long long acc[8] = {0, 0, 0, 0, 0, 0, 0, 0};
#pragma unroll 1
        for (int t = 0; t < 27; t++) {
            int dz = t / 9 - 1, dy = (t / 3) % 3 - 1, dx = t % 3 - 1;
            int za = z + dz, ya = y + dy, xa = x + dx;
            bool v0 = (unsigned)za < (unsigned)S && (unsigned)ya < (unsigned)S && (unsigned)xa < (unsigned)S;
            float4 A = Z;
            if (v0) A = ((const float4*)(in + (size_t)((((za << sb) + ya) << sb) + xa) * 16))[q];
            const ulonglong2* wq = (const ulonglong2*)(sw + t * 272 + q * 68);
#pragma unroll
            for (int j = 0; j < 4; j++) {
                unsigned long long pa = pack2s(comp4(A, j));
                const ulonglong2* wr = wq + j * 4;
                ulonglong2 w01 = wr[0], w23 = wr[1], w45 = wr[2], w67 = wr[3];
                fma2(acc[0], pa, w01.x); fma2(acc[1], pa, w01.y);
                fma2(acc[2], pa, w23.x); fma2(acc[3], pa, w23.y);
                fma2(acc[4], pa, w45.x); fma2(acc[5], pa, w45.y);
                fma2(acc[6], pa, w67.x); fma2(acc[7], pa, w67.y);
            }
        }
        // unpack to 16 floats, 2-stage quad butterfly
        float f[16];
#pragma unroll
        for (int p = 0; p < 8; p++) {
            float2 v2 = unpack2(acc[p]);
            f[2 * p] = v2.x; f[2 * p + 1] = v2.y;
        }
#pragma unroll
        for (int d = 1; d <= 2; d <<= 1)
#pragma unroll
            for (int k = 0; k < 16; k++)
                f[k] += __shfl_xor_sync(0xffffffffu, f[k], d);
        if (live) {
            float4 bb = __ldg((const float4*)b + q);
            float4 r = make_float4(fmaxf(f[4 * q + 0] + bb.x, 0.f),
                                   fmaxf(f[4 * q + 1] + bb.y, 0.f),
                                   fmaxf(f[4 * q + 2] + bb.z, 0.f),
                                   fmaxf(f[4 * q + 3] + bb.w, 0.f));
            ((float4*)(out + (size_t)idx * 16))[q] = r;
        }
    }
}

// cls conv 16->1, QUAD REMAP; zeroes g_hist2
__global__ __launch_bounds__(256) void k_cls16(const float* __restrict__ in,
                                               const float* __restrict__ w,
                                               const float* __restrict__ b,
                                               float* __restrict__ outp,
                                               const int* __restrict__ list, int S, int sb) {
    __shared__ float sw[432];
    for (int i = threadIdx.x; i < 432; i += blockDim.x) sw[i] = w[i];
    __syncthreads();
    int n = g_ncand;
    int tid = blockIdx.x * blockDim.x + threadIdx.x;
    if (tid < 2048) ((unsigned int*)g_hist2)[tid] = 0u;
    int lane = threadIdx.x & 31;
    int q = lane & 3;
    int sub = lane >> 2;
    int wgv = tid >> 5;
    int wstride = (gridDim.x * blockDim.x) >> 5;
    int M = S - 1;
    float bias = __ldg(b);
    const float4 Z = make_float4(0.f, 0.f, 0.f, 0.f);
    for (int base = wgv * 8; base < n; base += wstride * 8) {
        int i = base + sub;
        bool live = i < n;
        int idx = list[live ? i : (n - 1)];
        int z = idx >> (2 * sb), y = (idx >> sb) & M, x = idx & M;
        float acc = 0.f;
#pragma unroll 1
        for (int t = 0; t < 27; t++) {
            int dz = t / 9 - 1, dy = (t / 3) % 3 - 1, dx = t % 3 - 1;
            int zz = z + dz, yy = y + dy, xx = x + dx;
            bool v0 = (unsigned)zz < (unsigned)S && (unsigned)yy < (unsigned)S && (unsigned)xx < (unsigned)S;
            float4 A = Z;
            if (v0) A = ((const float4*)(in + (size_t)((((zz << sb) + yy) << sb) + xx) * 16))[q];
            float4 wv = ((const float4*)(sw + t * 16))[q];
            acc = fmaf(A.x, wv.x, acc); acc = fmaf(A.y, wv.y, acc);
            acc = fmaf(A.z, wv.z, acc); acc = fmaf(A.w, wv.w, acc);
        }
        acc += __shfl_xor_sync(0xffffffffu, acc, 1);
        acc += __shfl_xor_sync(0xffffffffu, acc, 2);
        acc += bias;
        if (live && q == 0) {
            outp[idx] = acc;
            g_keys[i] = make_key(acc, idx);
        }
    }
}

// conv_transpose 2x (flipped kernel), relu, packed FFMA2, PADDED oct stride (260)
__global__ __launch_bounds__(256) void k_up(const float* __restrict__ feat,
                                            const float* __restrict__ w,
                                            const float* __restrict__ b,
                                            float* __restrict__ hout,
                                            const int* __restrict__ list, int sb) {
    __shared__ float sw[WUPAD];
    for (int i = threadIdx.x; i < WUPAD; i += blockDim.x) {
        int oct = i / 260, rr = i % 260;
        sw[i] = (rr < 256) ? w[oct * 256 + rr] : 0.f;
    }
    __syncthreads();
    int n = g_ncand;
    int sbc = sb + 1;
    int Mc = (1 << sbc) - 1;
    int stride = gridDim.x * blockDim.x;
    for (int i = blockIdx.x * blockDim.x + threadIdx.x; i < n; i += stride) {
        int cidx = list[i];
        int cz = cidx >> (2 * sbc), cy = (cidx >> sbc) & Mc, cx = cidx & Mc;
        int j = ((cz & 1) << 2) | ((cy & 1) << 1) | (cx & 1);
        int pidx = ((((cz >> 1) << sb) + (cy >> 1)) << sb) + (cx >> 1);
        const ulonglong2* wt = (const ulonglong2*)(sw + (7 - j) * 260);
        const float4* fp4 = (const float4*)(feat + (size_t)pidx * 16);
        unsigned long long acc[8];
        {
            const float2* b2 = (const float2*)b;
#pragma unroll
            for (int p = 0; p < 8; p++) {
                float2 bv = __ldg(b2 + p);
                acc[p] = pack2(bv.x, bv.y);
            }
        }
#pragma unroll
        for (int q = 0; q < 4; q++) {
            float4 A = fp4[q];
#pragma unroll
            for (int jj = 0; jj < 4; jj++) {
                unsigned long long pa = pack2s(comp4(A, jj));
                const ulonglong2* wr = wt + (4 * q + jj) * 4;
                ulonglong2 w01 = wr[0], w23 = wr[1], w45 = wr[2], w67 = wr[3];
                fma2(acc[0], pa, w01.x); fma2(acc[1], pa, w01.y);
                fma2(acc[2], pa, w23.x); fma2(acc[3], pa, w23.y);
                fma2(acc[4], pa, w45.x); fma2(acc[5], pa, w45.y);
                fma2(acc[6], pa, w67.x); fma2(acc[7], pa, w67.y);
            }
        }
        float4* op = (float4*)(hout + (size_t)cidx * 16);
#pragma unroll
        for (int p = 0; p < 4; p++) {
            float2 lo = unpack2(acc[2 * p]);
            float2 hi = unpack2(acc[2 * p + 1]);
            op[p] = make_float4(fmaxf(lo.x, 0.f), fmaxf(lo.y, 0.f),
                                fmaxf(hi.x, 0.f), fmaxf(hi.y, 0.f));
        }
    }
}

extern "C" void kernel_launch(void* const* d_in, const int* in_sizes, int n_in,
                              void* d_out, int out_size) {
    const float* x   = (const float*)d_in[0];
    const void* occ0 = d_in[1];
    const void* gt0  = d_in[2];
    const void* gt1  = d_in[3];
    const void* gt2  = d_in[4];
    const float* wc0 = (const float*)d_in[5],  *bc0 = (const float*)d_in[6];
    const float* wk0 = (const float*)d_in[7],  *bk0 = (const float*)d_in[8];
    const float* wu1 = (const float*)d_in[9],  *bu1 = (const float*)d_in[10];
    const float* wc1 = (const float*)d_in[11], *bc1 = (const float*)d_in[12];
    const float* wk1 = (const float*)d_in[13], *bk1 = (const float*)d_in[14];
    const float* wu2 = (const float*)d_in[15], *bu2 = (const float*)d_in[16];
    const float* wc2 = (const float*)d_in[17], *bc2 = (const float*)d_in[18];
    const float* wk2 = (const float*)d_in[19], *bk2 = (const float*)d_in[20];
    const int* n0 = (const int*)d_in[21];
    const int* n1 = (const int*)d_in[22];
    const int* n2 = (const int*)d_in[23];
    float* out = (float*)d_out;

    int *dlist0, *dlist1, *dlist2;
    cudaGetSymbolAddress((void**)&dlist0, g_list0);
    cudaGetSymbolAddress((void**)&dlist1, g_list1);
    cudaGetSymbolAddress((void**)&dlist2, g_list2);
    float *dh1, *dh2, *df0, *df1;
    cudaGetSymbolAddress((void**)&dh1, g_h1);
    cudaGetSymbolAddress((void**)&dh2, g_h2);
    cudaGetSymbolAddress((void**)&df0, g_feat0);
    cudaGetSymbolAddress((void**)&df1, g_feat1);
    unsigned char *dg0, *dg1, *dg2, *do0, *do1, *do2;
    cudaGetSymbolAddress((void**)&dg0, g_gt0);
    cudaGetSymbolAddress((void**)&dg1, g_gt1);
    cudaGetSymbolAddress((void**)&dg2, g_gt2);
    cudaGetSymbolAddress((void**)&do0, g_occ0);
    cudaGetSymbolAddress((void**)&do1, g_occ1);
    cudaGetSymbolAddress((void**)&do2, g_occ2);

    static int smem_set = 0;
    if (!smem_set) {
        cudaFuncSetAttribute(k_conv0, cudaFuncAttributeMaxDynamicSharedMemorySize,
                             W0PAD * (int)sizeof(float));
        smem_set = 1;
    }

    k_detect<<<1, 256>>>((const unsigned char*)occ0, n0, n1, n2);    // 0
    k_cvt<<<2368, 1024>>>(occ0, gt0, gt1, gt2);                      // 1
    k_compact<<<GSB, GST>>>(do0, dlist0, V0, 0);                     // 2
    k_conv0<<<444, 256, W0PAD * sizeof(float)>>>(x, wc0, bc0);       // 3 <- profiled
    k_zero_out<<<2048, 256>>>((float4*)out);
    k_cls16<<<592, 256>>>(df0, wk0, bk0, out, dlist0, 32, 5);
    k_select<<<GSB, GST>>>(dlist0, dg0, nullptr, do1, 0, 5, 1);

    // ---- level 1 ----
    k_compact<<<GSB, GST>>>(do1, dlist1, V1, 2);
    k_up<<<1024, 256>>>(df0, wu1, bu1, dh1, dlist1, 5);
    k_conv16<<<2048, 256>>>(dh1, wc1, bc1, df1, dlist1, 64, 6);
    k_cls16<<<1024, 256>>>(df1, wk1, bk1, out + OFF_CLS1, dlist1, 64, 6);
    k_select<<<GSB, GST>>>(dlist1, dg1, nullptr, do2, 1, 6, 3);

    // ---- level 2 ----
    k_compact<<<GSB, GST>>>(do2, dlist2, V2, 4);
    k_up<<<2048, 256>>>(df1, wu2, bu2, dh2, dlist2, 6);
    k_conv16<<<4096, 256>>>(dh2, wc2, bc2, out + OFF_OUT, dlist2, 128, 7);
    k_cls16<<<2048, 256>>>(out + OFF_OUT, wk2, bk2, out + OFF_CLS2, dlist2, 128, 7);
    k_select<<<GSB, GST>>>(dlist2, dg2, out + OFF_OUT, do2, 2, 7, 5);
}

// round 16
// speedup vs baseline: 1.1292x; 1.1292x over previous
#include <cuda_runtime.h>

#define V0 32768
#define V1 262144
#define V2 2097152
#define OFF_CLS1 32768
#define OFF_CLS2 294912
#define OFF_OUT  2392064
#define NF4 8986624
#define GSB 128
#define GST 256
#define W0PAD 14688  // conv0: 27*544 floats
#define WUPAD 2080   // up: 8*260 floats

__device__ float g_feat0[V0 * 16];
__device__ float g_h1[V1 * 16];
__device__ float g_feat1[V1 * 16];
__device__ float g_h2[V2 * 16];
__device__ unsigned char g_occ0[V0], g_gt0[V0], g_gt1[V1], g_gt2[V2];
__device__ unsigned char g_occ1[V1], g_occ2[V2];
__device__ int g_list0[V0], g_list1[V1], g_list2[V2];
__device__ unsigned long long g_keys[V2];
__device__ unsigned int g_hist2[8][256];
__device__ int g_bsum[GSB];
__device__ unsigned int g_syncbar[8];
__device__ int g_mode, g_karr[3], g_ncand;

__device__ __forceinline__ unsigned long long make_key(float f, int idx) {
    unsigned int u = __float_as_uint(f);
    unsigned int m = (u & 0x80000000u) ? ~u : (u | 0x80000000u);
    return ((unsigned long long)m << 32) | (unsigned int)(~(unsigned int)idx);
}

__device__ __forceinline__ float4 fma4(float a, float4 w, float4 c) {
    c.x = fmaf(a, w.x, c.x); c.y = fmaf(a, w.y, c.y);
    c.z = fmaf(a, w.z, c.z); c.w = fmaf(a, w.w, c.w);
    return c;
}

__device__ __forceinline__ float comp4(float4 v, int j) {
    return j == 0 ? v.x : (j == 1 ? v.y : (j == 2 ? v.z : v.w));
}

// ---- packed f32x2 helpers ----
__device__ __forceinline__ unsigned long long pack2s(float a) {
    unsigned long long r;
    asm("mov.b64 %0, {%1, %1};" : "=l"(r) : "f"(a));
    return r;
}
__device__ __forceinline__ unsigned long long pack2(float lo, float hi) {
    unsigned long long r;
    asm("mov.b64 %0, {%1, %2};" : "=l"(r) : "f"(lo), "f"(hi));
    return r;
}
__device__ __forceinline__ void fma2(unsigned long long& c, unsigned long long a,
                                     unsigned long long w) {
    asm("fma.rn.f32x2 %0, %1, %2, %0;" : "+l"(c) : "l"(a), "l"(w));
}
__device__ __forceinline__ float2 unpack2(unsigned long long v) {
    float lo, hi;
    asm("mov.b64 {%0, %1}, %2;" : "=f"(lo), "=f"(hi) : "l"(v));
    return make_float2(lo, hi);
}

__device__ __forceinline__ void oreduce(float4& v) {
#pragma unroll
    for (int d = 1; d <= 4; d <<= 1) {
        v.x += __shfl_xor_sync(0xffffffffu, v.x, d);
        v.y += __shfl_xor_sync(0xffffffffu, v.y, d);
        v.z += __shfl_xor_sync(0xffffffffu, v.z, d);
        v.w += __shfl_xor_sync(0xffffffffu, v.w, d);
    }
}

__device__ __forceinline__ void gsync(int slot, int* cnt) {
    __syncthreads();
    if (threadIdx.x == 0) {
        (*cnt)++;
        __threadfence();
        atomicAdd(&g_syncbar[slot], 1u);
        unsigned int target = (unsigned int)(*cnt) * GSB;
        while (*(volatile unsigned int*)&g_syncbar[slot] < target) { }
        __threadfence();
    }
    __syncthreads();
}

__global__ void k_zero_out(float4* __restrict__ out) {
    int stride = gridDim.x * blockDim.x;
    for (int i = blockIdx.x * blockDim.x + threadIdx.x; i < NF4; i += stride)
        out[i] = make_float4(0.f, 0.f, 0.f, 0.f);
}

__global__ void k_detect(const unsigned char* __restrict__ occ0b,
                         const int* __restrict__ k0p, const int* __restrict__ k1p,
                         const int* __restrict__ k2p) {
    __shared__ int s_not01, s_off4;
    if (threadIdx.x == 0) { s_not01 = 0; s_off4 = 0; }
    __syncthreads();
    for (int i = threadIdx.x; i < 32768; i += 256) {
        unsigned char c = occ0b[i];
        if (c > 1) s_not01 = 1;
        else if (c == 1 && (i & 3)) s_off4 = 1;
    }
    if (threadIdx.x < 8) g_syncbar[threadIdx.x] = 0u;
    __syncthreads();
    if (threadIdx.x == 0) {
        g_mode = s_not01 ? 2 : (s_off4 ? 0 : 1);
        int w;
        w = k0p[0]; g_karr[0] = (w > 0 && w < (1 << 26)) ? w : 8192;
        w = k1p[0]; g_karr[1] = (w > 0 && w < (1 << 26)) ? w : 32768;
        w = k2p[0]; g_karr[2] = (w > 0 && w < (1 << 26)) ? w : 131072;
    }
}

__global__ void k_cvt(const void* __restrict__ occ0p, const void* __restrict__ gt0p,
                      const void* __restrict__ gt1p, const void* __restrict__ gt2p) {
    int mode = g_mode;
    int stride = gridDim.x * blockDim.x;
    for (int i = blockIdx.x * blockDim.x + threadIdx.x; i < 2 * V0 + V1 + V2; i += stride) {
        const void* src; unsigned char* dst; int li;
        if (i < V0)                 { src = occ0p; dst = g_occ0; li = i; }
        else if (i < 2 * V0)        { src = gt0p;  dst = g_gt0;  li = i - V0; }
        else if (i < 2 * V0 + V1)   { src = gt1p;  dst = g_gt1;  li = i - 2 * V0; }
        else                        { src = gt2p;  dst = g_gt2;  li = i - 2 * V0 - V1; }
        unsigned char v;
        if (mode == 0)      v = ((const unsigned char*)src)[li] != 0;
        else if (mode == 1) v = ((const int*)src)[li] != 0;
        else                v = ((const float*)src)[li] != 0.0f;
        dst[li] = v;
    }
}

// fused count + redundant prefix + ordered write (ONE gsync)
__global__ __launch_bounds__(GST) void k_compact(const unsigned char* __restrict__ occ,
                                                 int* __restrict__ list, int N, int slot) {
    int sc = 0;
    int chunk = N / GSB;
    int base = blockIdx.x * chunk;
    int t = threadIdx.x;
    __shared__ int s[GST];
    int sum = 0;
    for (int i = t; i < chunk; i += GST) sum += occ[base + i] ? 1 : 0;
    s[t] = sum;
    __syncthreads();
    for (int off = GST / 2; off > 0; off >>= 1) {
        if (t < off) s[t] += s[t + off];
        __syncthreads();
    }
    if (t == 0) *(volatile int*)&g_bsum[blockIdx.x] = s[0];
    gsync(slot, &sc);
    __shared__ unsigned int ps[GSB];
    if (t < GSB) ps[t] = (unsigned int)(*(volatile int*)&g_bsum[t]);
    __syncthreads();
    for (int off = 1; off < GSB; off <<= 1) {
        unsigned int v = (t < GSB && t >= off) ? ps[t - off] : 0u;
        __syncthreads();
        if (t < GSB) ps[t] += v;
        __syncthreads();
    }
    if (blockIdx.x == 0 && t == 0) g_ncand = (int)ps[GSB - 1];
    __shared__ int s_base;
    __shared__ int warpcnt[GST / 32];
    if (t == 0) s_base = (blockIdx.x == 0) ? 0 : (int)ps[blockIdx.x - 1];
    __syncthreads();
    int wid = t >> 5, lane = t & 31;
    for (int off = 0; off < chunk; off += GST) {
        int j = off + t;
        int v = (j < chunk) ? (occ[base + j] ? 1 : 0) : 0;
        unsigned int bal = __ballot_sync(0xffffffffu, v);
        if (lane == 0) warpcnt[wid] = __popc(bal);
        __syncthreads();
        int wbase = s_base;
        for (int w = 0; w < wid; w++) wbase += warpcnt[w];
        if (v) list[wbase + __popc(bal & ((1u << lane) - 1u))] = base + j;
        __syncthreads();
        if (t == 0) {
            int tot = 0;
            for (int w = 0; w < GST / 32; w++) tot += warpcnt[w];
            s_base += tot;
        }
        __syncthreads();
    }
}

// fused radix select: ONE gsync per pass, redundant scan in every block
__global__ __launch_bounds__(GST) void k_select(const int* __restrict__ list,
                                                const unsigned char* __restrict__ gt,
                                                float* __restrict__ outfeat,
                                                unsigned char* __restrict__ occn,
                                                int level, int sb, int slot) {
    int sc = 0;
    int n = g_ncand;
    int t = threadIdx.x;
    int gtid = blockIdx.x * GST + t;
    int gstride = GSB * GST;
    __shared__ unsigned int sh[256], ss[256];
    __shared__ unsigned int s_krem;
    __shared__ int s_all, s_done;
    __shared__ unsigned long long s_pre;
    if (t == 0) { s_all = 0; s_done = 0; s_pre = 0ULL; s_krem = 0u; }
    __syncthreads();
    int all = 0, done = 0;
    unsigned int krem = 0;
    unsigned long long pre = 0ULL;
    for (int pass = 0; pass < 8; pass++) {
        int shift = 56 - 8 * pass;
        if (!all) {
            sh[t] = 0u;
            __syncthreads();
            for (int i = gtid; i < n; i += gstride) {
                unsigned long long key = g_keys[i];
                if (pass > 0 && ((key ^ pre) >> (shift + 8))) continue;
                atomicAdd(&sh[(unsigned int)(key >> shift) & 255u], 1u);
            }
            __syncthreads();
            if (sh[t]) atomicAdd(&g_hist2[pass][t], sh[t]);
        }
        gsync(slot, &sc);
        unsigned int cnt = g_hist2[pass][t];
        ss[t] = cnt;
        __syncthreads();
        for (int off = 1; off < 256; off <<= 1) {
            unsigned int v = (t + off < 256) ? ss[t + off] : 0u;
            __syncthreads();
            ss[t] += v;
            __syncthreads();
        }
        if (pass == 0) {
            if (t == 0) {
                s_krem = (unsigned int)g_karr[level];
                if (ss[0] <= s_krem) { s_all = 1; s_done = 1; }
            }
            __syncthreads();
            all = s_all; done = s_done; krem = s_krem;
        }
        if (!all) {
            unsigned int kr = krem;
            if (ss[t] >= kr && (t == 255 || ss[t + 1] < kr)) {
                unsigned int above = (t < 255) ? ss[t + 1] : 0u;
                unsigned int krn = kr - above;
                s_pre = pre | ((unsigned long long)t << shift);
                s_krem = krn;
                if (cnt == krn) s_done = 1;
            }
            __syncthreads();
            pre = s_pre; krem = s_krem; done = s_done;
            __syncthreads();
        }
        if (done) break;
    }
    unsigned long long thr = pre;
    int M = (1 << sb) - 1, sbc = sb + 1;
    for (int i = gtid; i < n; i += gstride) {
        int idx = list[i];
        bool m = all || (g_keys[i] >= thr) || gt[idx];
        if (level < 2) {
            if (m) {
                int z = idx >> (2 * sb), y = (idx >> sb) & M, x = idx & M;
                int zb = z << 1, yb = y << 1, xb = x << 1;
#pragma unroll
                for (int dz = 0; dz < 2; dz++)
#pragma unroll
                    for (int dy = 0; dy < 2; dy++) {
                        int o = ((((zb + dz) << sbc) + (yb + dy)) << sbc) + xb;
                        *(unsigned short*)(occn + o) = 0x0101;
                    }
            }
        } else if (!m) {
            float4* p = (float4*)(outfeat + (size_t)idx * 16);
            float4 Z = make_float4(0.f, 0.f, 0.f, 0.f);
            p[0] = Z; p[1] = Z; p[2] = Z; p[3] = Z;
        }
    }
}

// conv0: 32 -> 16, S=32, relu; 8 lanes/voxel; padded smem weights
__global__ __launch_bounds__(256) void k_conv0(const float* __restrict__ x,
                                               const float* __restrict__ w,
                                               const float* __restrict__ b) {
    extern __shared__ float swc[];
    for (int i = threadIdx.x; i < W0PAD; i += 256) {
        int t = i / 544, r = i % 544;
        int sub = r / 68, rr = r % 68;
        swc[i] = (rr < 64) ? w[t * 512 + sub * 64 + rr] : 0.f;
    }
    __syncthreads();
    int n = g_ncand;
    int lane = threadIdx.x & 31;
    int sub = lane & 7;
    int grp = lane >> 3;
    int gw = (blockIdx.x * blockDim.x + threadIdx.x) >> 5;
    int wstride = (gridDim.x * blockDim.x) >> 5;
    const float4 Z = make_float4(0.f, 0.f, 0.f, 0.f);
    for (int base = gw * 4; base < n; base += wstride * 4) {
        int v = base + grp;
        bool live = v < n;
        int idx = g_list0[live ? v : (n - 1)];
        int z = idx >> 10, y = (idx >> 5) & 31, xx = idx & 31;
        float4 acc[4] = {Z, Z, Z, Z};
#pragma unroll 1
        for (int t = 0; t < 27; t++) {
            int dz = t / 9 - 1, dy = (t / 3) % 3 - 1, dx = t % 3 - 1;
            int zz = z + dz, yy = y + dy, xc = xx + dx;
            if ((unsigned)zz >= 32u || (unsigned)yy >= 32u || (unsigned)xc >= 32u) continue;
            const float4* ip4 = (const float4*)(x + ((((zz << 5) + yy) << 5) + xc) * 32);
            float4 A = __ldg(ip4 + sub);
            const float4* wp4 = (const float4*)(swc + t * 544 + sub * 68);
#pragma unroll
            for (int cc = 0; cc < 4; cc++) {
                float a = comp4(A, cc);
                const float4* wr = wp4 + cc * 4;
                acc[0] = fma4(a, wr[0], acc[0]);
                acc[1] = fma4(a, wr[1], acc[1]);
                acc[2] = fma4(a, wr[2], acc[2]);
                acc[3] = fma4(a, wr[3], acc[3]);
            }
        }
        oreduce(acc[0]); oreduce(acc[1]); oreduce(acc[2]); oreduce(acc[3]);
        if (live && sub < 4) {
            float4 bb = __ldg((const float4*)b + sub);
            float4 av = acc[sub];
            float4 r = make_float4(fmaxf(av.x + bb.x, 0.f), fmaxf(av.y + bb.y, 0.f),
                                   fmaxf(av.z + bb.z, 0.f), fmaxf(av.w + bb.w, 0.f));
            ((float4*)(g_feat0 + idx * 16))[sub] = r;
        }
    }
}

// 16->16 conv3x3 over list, relu, 1 voxel/thread, packed FFMA2 (R14 form — broadcast weights)
__global__ __launch_bounds__(256) void k_conv16(const float* __restrict__ in,
                                                const float* __restrict__ w,
                                                const float* __restrict__ b,
                                                float* __restrict__ out,
                                                const int* __restrict__ list, int S, int sb) {
    __shared__ float sw[6912];
    for (int i = threadIdx.x; i < 6912; i += blockDim.x) sw[i] = w[i];
    __syncthreads();
    int n = g_ncand;
    int stride = gridDim.x * blockDim.x;
    int M = S - 1;
    const float4 Z = make_float4(0.f, 0.f, 0.f, 0.f);
    for (int i = blockIdx.x * blockDim.x + threadIdx.x; i < n; i += stride) {
        int idx0 = list[i];
        int z0 = idx0 >> (2 * sb), y0 = (idx0 >> sb) & M, x0 = idx0 & M;
        unsigned long long acc[8];
        {
            const float2* b2 = (const float2*)b;
#pragma unroll
            for (int p = 0; p < 8; p++) {
                float2 bv = __ldg(b2 + p);
                acc[p] = pack2(bv.x, bv.y);
            }
        }
#pragma unroll 1
        for (int t = 0; t < 27; t++) {
            int dz = t / 9 - 1, dy = (t / 3) % 3 - 1, dx = t % 3 - 1;
            int za = z0 + dz, ya = y0 + dy, xa = x0 + dx;
            bool v0 = (unsigned)za < (unsigned)S && (unsigned)ya < (unsigned)S && (unsigned)xa < (unsigned)S;
            const float4* p0 = (const float4*)(in + (size_t)((((za << sb) + ya) << sb) + xa) * 16);
            const ulonglong2* wt = (const ulonglong2*)(sw + t * 256);
#pragma unroll
            for (int q = 0; q < 4; q++) {
                float4 A = v0 ? p0[q] : Z;
#pragma unroll
                for (int j = 0; j < 4; j++) {
                    unsigned long long pa = pack2s(comp4(A, j));
                    const ulonglong2* wr = wt + (4 * q + j) * 4;
                    ulonglong2 w01 = wr[0], w23 = wr[1], w45 = wr[2], w67 = wr[3];
                    fma2(acc[0], pa, w01.x); fma2(acc[1], pa, w01.y);
                    fma2(acc[2], pa, w23.x); fma2(acc[3], pa, w23.y);
                    fma2(acc[4], pa, w45.x); fma2(acc[5], pa, w45.y);
                    fma2(acc[6], pa, w67.x); fma2(acc[7], pa, w67.y);
                }
            }
        }
        float4* o4 = (float4*)(out + (size_t)idx0 * 16);
#pragma unroll
        for (int p = 0; p < 4; p++) {
            float2 lo = unpack2(acc[2 * p]);
            float2 hi = unpack2(acc[2 * p + 1]);
            o4[p] = make_float4(fmaxf(lo.x, 0.f), fmaxf(lo.y, 0.f),
                                fmaxf(hi.x, 0.f), fmaxf(hi.y, 0.f));
        }
    }
}

// cls conv 16->1, QUAD REMAP; zeroes g_hist2
__global__ __launch_bounds__(256) void k_cls16(const float* __restrict__ in,
                                               const float* __restrict__ w,
                                               const float* __restrict__ b,
                                               float* __restrict__ outp,
                                               const int* __restrict__ list, int S, int sb) {
    __shared__ float sw[432];
    for (int i = threadIdx.x; i < 432; i += blockDim.x) sw[i] = w[i];
    __syncthreads();
    int n = g_ncand;
    int tid = blockIdx.x * blockDim.x + threadIdx.x;
    if (tid < 2048) ((unsigned int*)g_hist2)[tid] = 0u;
    int lane = threadIdx.x & 31;
    int q = lane & 3;
    int sub = lane >> 2;
    int wgv = tid >> 5;
    int wstride = (gridDim.x * blockDim.x) >> 5;
    int M = S - 1;
    float bias = __ldg(b);
    const float4 Z = make_float4(0.f, 0.f, 0.f, 0.f);
    for (int base = wgv * 8; base < n; base += wstride * 8) {
        int i = base + sub;
        bool live = i < n;
        int idx = list[live ? i : (n - 1)];
        int z = idx >> (2 * sb), y = (idx >> sb) & M, x = idx & M;
        float acc = 0.f;
#pragma unroll 1
        for (int t = 0; t < 27; t++) {
            int dz = t / 9 - 1, dy = (t / 3) % 3 - 1, dx = t % 3 - 1;
            int zz = z + dz, yy = y + dy, xx = x + dx;
            bool v0 = (unsigned)zz < (unsigned)S && (unsigned)yy < (unsigned)S && (unsigned)xx < (unsigned)S;
            float4 A = Z;
            if (v0) A = ((const float4*)(in + (size_t)((((zz << sb) + yy) << sb) + xx) * 16))[q];
            float4 wv = ((const float4*)(sw + t * 16))[q];
            acc = fmaf(A.x, wv.x, acc); acc = fmaf(A.y, wv.y, acc);
            acc = fmaf(A.z, wv.z, acc); acc = fmaf(A.w, wv.w, acc);
        }
        acc += __shfl_xor_sync(0xffffffffu, acc, 1);
        acc += __shfl_xor_sync(0xffffffffu, acc, 2);
        acc += bias;
        if (live && q == 0) {
            outp[idx] = acc;
            g_keys[i] = make_key(acc, idx);
        }
    }
}

// conv_transpose 2x (flipped kernel), relu, packed FFMA2, PADDED oct stride (260)
__global__ __launch_bounds__(256) void k_up(const float* __restrict__ feat,
                                            const float* __restrict__ w,
                                            const float* __restrict__ b,
                                            float* __restrict__ hout,
                                            const int* __restrict__ list, int sb) {
    __shared__ float sw[WUPAD];
    for (int i = threadIdx.x; i < WUPAD; i += blockDim.x) {
        int oct = i / 260, rr = i % 260;
        sw[i] = (rr < 256) ? w[oct * 256 + rr] : 0.f;
    }
    __syncthreads();
    int n = g_ncand;
    int sbc = sb + 1;
    int Mc = (1 << sbc) - 1;
    int stride = gridDim.x * blockDim.x;
    for (int i = blockIdx.x * blockDim.x + threadIdx.x; i < n; i += stride) {
        int cidx = list[i];
        int cz = cidx >> (2 * sbc), cy = (cidx >> sbc) & Mc, cx = cidx & Mc;
        int j = ((cz & 1) << 2) | ((cy & 1) << 1) | (cx & 1);
        int pidx = ((((cz >> 1) << sb) + (cy >> 1)) << sb) + (cx >> 1);
        const ulonglong2* wt = (const ulonglong2*)(sw + (7 - j) * 260);
        const float4* fp4 = (const float4*)(feat + (size_t)pidx * 16);
        unsigned long long acc[8];
        {
            const float2* b2 = (const float2*)b;
#pragma unroll
            for (int p = 0; p < 8; p++) {
                float2 bv = __ldg(b2 + p);
                acc[p] = pack2(bv.x, bv.y);
            }
        }
#pragma unroll
        for (int q = 0; q < 4; q++) {
            float4 A = fp4[q];
#pragma unroll
            for (int jj = 0; jj < 4; jj++) {
                unsigned long long pa = pack2s(comp4(A, jj));
                const ulonglong2* wr = wt + (4 * q + jj) * 4;
                ulonglong2 w01 = wr[0], w23 = wr[1], w45 = wr[2], w67 = wr[3];
                fma2(acc[0], pa, w01.x); fma2(acc[1], pa, w01.y);
                fma2(acc[2], pa, w23.x); fma2(acc[3], pa, w23.y);
                fma2(acc[4], pa, w45.x); fma2(acc[5], pa, w45.y);
                fma2(acc[6], pa, w67.x); fma2(acc[7], pa, w67.y);
            }
        }
        float4* op = (float4*)(hout + (size_t)cidx * 16);
#pragma unroll
        for (int p = 0; p < 4; p++) {
            float2 lo = unpack2(acc[2 * p]);
            float2 hi = unpack2(acc[2 * p + 1]);
            op[p] = make_float4(fmaxf(lo.x, 0.f), fmaxf(lo.y, 0.f),
                                fmaxf(hi.x, 0.f), fmaxf(hi.y, 0.f));
        }
    }
}

extern "C" void kernel_launch(void* const* d_in, const int* in_sizes, int n_in,
                              void* d_out, int out_size) {
    const float* x   = (const float*)d_in[0];
    const void* occ0 = d_in[1];
    const void* gt0  = d_in[2];
    const void* gt1  = d_in[3];
    const void* gt2  = d_in[4];
    const float* wc0 = (const float*)d_in[5],  *bc0 = (const float*)d_in[6];
    const float* wk0 = (const float*)d_in[7],  *bk0 = (const float*)d_in[8];
    const float* wu1 = (const float*)d_in[9],  *bu1 = (const float*)d_in[10];
    const float* wc1 = (const float*)d_in[11], *bc1 = (const float*)d_in[12];
    const float* wk1 = (const float*)d_in[13], *bk1 = (const float*)d_in[14];
    const float* wu2 = (const float*)d_in[15], *bu2 = (const float*)d_in[16];
    const float* wc2 = (const float*)d_in[17], *bc2 = (const float*)d_in[18];
    const float* wk2 = (const float*)d_in[19], *bk2 = (const float*)d_in[20];
    const int* n0 = (const int*)d_in[21];
    const int* n1 = (const int*)d_in[22];
    const int* n2 = (const int*)d_in[23];
    float* out = (float*)d_out;

    int *dlist0, *dlist1, *dlist2;
    cudaGetSymbolAddress((void**)&dlist0, g_list0);
    cudaGetSymbolAddress((void**)&dlist1, g_list1);
    cudaGetSymbolAddress((void**)&dlist2, g_list2);
    float *dh1, *dh2, *df0, *df1;
    cudaGetSymbolAddress((void**)&dh1, g_h1);
    cudaGetSymbolAddress((void**)&dh2, g_h2);
    cudaGetSymbolAddress((void**)&df0, g_feat0);
    cudaGetSymbolAddress((void**)&df1, g_feat1);
    unsigned char *dg0, *dg1, *dg2, *do0, *do1, *do2;
    cudaGetSymbolAddress((void**)&dg0, g_gt0);
    cudaGetSymbolAddress((void**)&dg1, g_gt1);
    cudaGetSymbolAddress((void**)&dg2, g_gt2);
    cudaGetSymbolAddress((void**)&do0, g_occ0);
    cudaGetSymbolAddress((void**)&do1, g_occ1);
    cudaGetSymbolAddress((void**)&do2, g_occ2);

    static int smem_set = 0;
    if (!smem_set) {
        cudaFuncSetAttribute(k_conv0, cudaFuncAttributeMaxDynamicSharedMemorySize,
                             W0PAD * (int)sizeof(float));
        smem_set = 1;
    }

    k_detect<<<1, 256>>>((const unsigned char*)occ0, n0, n1, n2);    // 0
    k_cvt<<<2368, 1024>>>(occ0, gt0, gt1, gt2);                      // 1
    k_compact<<<GSB, GST>>>(do0, dlist0, V0, 0);                     // 2
    k_conv0<<<444, 256, W0PAD * sizeof(float)>>>(x, wc0, bc0);       // 3 <- profiled
    k_zero_out<<<2048, 256>>>((float4*)out);
    k_cls16<<<592, 256>>>(df0, wk0, bk0, out, dlist0, 32, 5);
    k_select<<<GSB, GST>>>(dlist0, dg0, nullptr, do1, 0, 5, 1);

    // ---- level 1 ----
    k_compact<<<GSB, GST>>>(do1, dlist1, V1, 2);
    k_up<<<1024, 256>>>(df0, wu1, bu1, dh1, dlist1, 5);
    k_conv16<<<1024, 256>>>(dh1, wc1, bc1, df1, dlist1, 64, 6);
    k_cls16<<<1024, 256>>>(df1, wk1, bk1, out + OFF_CLS1, dlist1, 64, 6);
    k_select<<<GSB, GST>>>(dlist1, dg1, nullptr, do2, 1, 6, 3);

    // ---- level 2 ----
    k_compact<<<GSB, GST>>>(do2, dlist2, V2, 4);
    k_up<<<2048, 256>>>(df1, wu2, bu2, dh2, dlist2, 6);
    k_conv16<<<2048, 256>>>(dh2, wc2, bc2, out + OFF_OUT, dlist2, 128, 7);
    k_cls16<<<2048, 256>>>(out + OFF_OUT, wk2, bk2, out + OFF_CLS2, dlist2, 128, 7);
    k_select<<<GSB, GST>>>(dlist2, dg2, out + OFF_OUT, do2, 2, 7, 5);
}

// round 17
// speedup vs baseline: 1.1551x; 1.0230x over previous
#include <cuda_runtime.h>

#define V0 32768
#define V1 262144
#define V2 2097152
#define OFF_CLS1 32768
#define OFF_CLS2 294912
#define OFF_OUT  2392064
#define NF4 8986624
#define GSB 128
#define GST 256
#define W0PAD 14688
#define WUPAD 2080

__device__ float g_feat0[V0 * 16];
__device__ float g_h1[V1 * 16];
__device__ float g_feat1[V1 * 16];
__device__ float g_h2[V2 * 16];
__device__ unsigned char g_occ0[V0], g_gt0[V0], g_gt1[V1], g_gt2[V2];
__device__ unsigned char g_occ1[V1], g_occ2[V2];
__device__ int g_list0[V0], g_list1[V1], g_list2[V2];
__device__ unsigned long long g_keys[V2];
__device__ unsigned int g_hist2[8][256];
__device__ int g_bsum[GSB];
__device__ unsigned int g_syncbar[8];
__device__ int g_mode, g_karr[3], g_ncand;

__device__ __forceinline__ unsigned long long make_key(float f, int idx) {
    unsigned int u = __float_as_uint(f);
    unsigned int m = (u & 0x80000000u) ? ~u : (u | 0x80000000u);
    return ((unsigned long long)m << 32) | (unsigned int)(~(unsigned int)idx);
}

__device__ __forceinline__ float4 fma4(float a, float4 w, float4 c) {
    c.x = fmaf(a, w.x, c.x); c.y = fmaf(a, w.y, c.y);
    c.z = fmaf(a, w.z, c.z); c.w = fmaf(a, w.w, c.w);
    return c;
}

__device__ __forceinline__ float comp4(float4 v, int j) {
    return j == 0 ? v.x : (j == 1 ? v.y : (j == 2 ? v.z : v.w));
}

__device__ __forceinline__ unsigned long long pack2s(float a) {
    unsigned long long r;
    asm("mov.b64 %0, {%1, %1};" : "=l"(r) : "f"(a));
    return r;
}
__device__ __forceinline__ unsigned long long pack2(float lo, float hi) {
    unsigned long long r;
    asm("mov.b64 %0, {%1, %2};" : "=l"(r) : "f"(lo), "f"(hi));
    return r;
}
__device__ __forceinline__ void fma2(unsigned long long& c, unsigned long long a,
                                     unsigned long long w) {
    asm("fma.rn.f32x2 %0, %1, %2, %0;" : "+l"(c) : "l"(a), "l"(w));
}
__device__ __forceinline__ float2 unpack2(unsigned long long v) {
    float lo, hi;
    asm("mov.b64 {%0, %1}, %2;" : "=f"(lo), "=f"(hi) : "l"(v));
    return make_float2(lo, hi);
}

__device__ __forceinline__ void oreduce(float4& v) {
#pragma unroll
    for (int d = 1; d <= 4; d <<= 1) {
        v.x += __shfl_xor_sync(0xffffffffu, v.x, d);
        v.y += __shfl_xor_sync(0xffffffffu, v.y, d);
        v.z += __shfl_xor_sync(0xffffffffu, v.z, d);
        v.w += __shfl_xor_sync(0xffffffffu, v.w, d);
    }
}

__device__ __forceinline__ void gsync(int slot, int* cnt) {
    __syncthreads();
    if (threadIdx.x == 0) {
        (*cnt)++;
        __threadfence();
        atomicAdd(&g_syncbar[slot], 1u);
        unsigned int target = (unsigned int)(*cnt) * GSB;
        while (*(volatile unsigned int*)&g_syncbar[slot] < target) { }
        __threadfence();
    }
    __syncthreads();
}

__global__ void k_detect(const unsigned char* __restrict__ occ0b,
                         const int* __restrict__ k0p, const int* __restrict__ k1p,
                         const int* __restrict__ k2p) {
    __shared__ int s_not01, s_off4;
    if (threadIdx.x == 0) { s_not01 = 0; s_off4 = 0; }
    __syncthreads();
    for (int i = threadIdx.x; i < 32768; i += 256) {
        unsigned char c = occ0b[i];
        if (c > 1) s_not01 = 1;
        else if (c == 1 && (i & 3)) s_off4 = 1;
    }
    if (threadIdx.x < 8) g_syncbar[threadIdx.x] = 0u;
    __syncthreads();
    if (threadIdx.x == 0) {
        g_mode = s_not01 ? 2 : (s_off4 ? 0 : 1);
        int w;
        w = k0p[0]; g_karr[0] = (w > 0 && w < (1 << 26)) ? w : 8192;
        w = k1p[0]; g_karr[1] = (w > 0 && w < (1 << 26)) ? w : 32768;
        w = k2p[0]; g_karr[2] = (w > 0 && w < (1 << 26)) ? w : 131072;
    }
}

// fused: zero output buffer + convert bool inputs
__global__ void k_zero_cvt(float4* __restrict__ out,
                           const void* __restrict__ occ0p, const void* __restrict__ gt0p,
                           const void* __restrict__ gt1p, const void* __restrict__ gt2p) {
    int stride = gridDim.x * blockDim.x;
    int tid0 = blockIdx.x * blockDim.x + threadIdx.x;
    const float4 Z = make_float4(0.f, 0.f, 0.f, 0.f);
    for (int i = tid0; i < NF4; i += stride) out[i] = Z;
    int mode = g_mode;
    for (int i = tid0; i < 2 * V0 + V1 + V2; i += stride) {
        const void* src; unsigned char* dst; int li;
        if (i < V0)                 { src = occ0p; dst = g_occ0; li = i; }
        else if (i < 2 * V0)        { src = gt0p;  dst = g_gt0;  li = i - V0; }
        else if (i < 2 * V0 + V1)   { src = gt1p;  dst = g_gt1;  li = i - 2 * V0; }
        else                        { src = gt2p;  dst = g_gt2;  li = i - 2 * V0 - V1; }
        unsigned char v;
        if (mode == 0)      v = ((const unsigned char*)src)[li] != 0;
        else if (mode == 1) v = ((const int*)src)[li] != 0;
        else                v = ((const float*)src)[li] != 0.0f;
        dst[li] = v;
    }
}

// compact phases as a device function (count -> gsync -> redundant prefix -> write)
__device__ void compact_body(const unsigned char* __restrict__ occ, int* __restrict__ list,
                             int N, int slot, int* sc) {
    int chunk = N / GSB;
    int base = blockIdx.x * chunk;
    int t = threadIdx.x;
    __shared__ int s[GST];
    int sum = 0;
    for (int i = t; i < chunk; i += GST) sum += occ[base + i] ? 1 : 0;
    s[t] = sum;
    __syncthreads();
    for (int off = GST / 2; off > 0; off >>= 1) {
        if (t < off) s[t] += s[t + off];
        __syncthreads();
    }
    if (t == 0) *(volatile int*)&g_bsum[blockIdx.x] = s[0];
    gsync(slot, sc);
    __shared__ unsigned int ps[GSB];
    if (t < GSB) ps[t] = (unsigned int)(*(volatile int*)&g_bsum[t]);
    __syncthreads();
    for (int off = 1; off < GSB; off <<= 1) {
        unsigned int v = (t < GSB && t >= off) ? ps[t - off] : 0u;
        __syncthreads();
        if (t < GSB) ps[t] += v;
        __syncthreads();
    }
    if (blockIdx.x == 0 && t == 0) g_ncand = (int)ps[GSB - 1];
    __shared__ int s_base;
    __shared__ int warpcnt[GST / 32];
    if (t == 0) s_base = (blockIdx.x == 0) ? 0 : (int)ps[blockIdx.x - 1];
    __syncthreads();
    int wid = t >> 5, lane = t & 31;
    for (int off = 0; off < chunk; off += GST) {
        int j = off + t;
        int v = (j < chunk) ? (occ[base + j] ? 1 : 0) : 0;
        unsigned int bal = __ballot_sync(0xffffffffu, v);
        if (lane == 0) warpcnt[wid] = __popc(bal);
        __syncthreads();
        int wbase = s_base;
        for (int w = 0; w < wid; w++) wbase += warpcnt[w];
        if (v) list[wbase + __popc(bal & ((1u << lane) - 1u))] = base + j;
        __syncthreads();
        if (t == 0) {
            int tot = 0;
            for (int w = 0; w < GST / 32; w++) tot += warpcnt[w];
            s_base += tot;
        }
        __syncthreads();
    }
}

__global__ __launch_bounds__(GST) void k_compact(const unsigned char* __restrict__ occ,
                                                 int* __restrict__ list, int N, int slot) {
    int sc = 0;
    compact_body(occ, list, N, slot, &sc);
}

// fused radix select + filter, then (level<2) compact of the next level
__global__ __launch_bounds__(GST) void k_selcomp(const int* __restrict__ list,
                                                 const unsigned char* __restrict__ gt,
                                                 float* __restrict__ outfeat,
                                                 unsigned char* __restrict__ occn,
                                                 int* __restrict__ nextlist,
                                                 int level, int sb, int nextN, int slot) {
    int sc = 0;
    int n = g_ncand;
    int t = threadIdx.x;
    int gtid = blockIdx.x * GST + t;
    int gstride = GSB * GST;
    __shared__ unsigned int sh[256], ss[256];
    __shared__ unsigned int s_krem;
    __shared__ int s_all, s_done;
    __shared__ unsigned long long s_pre;
    if (t == 0) { s_all = 0; s_done = 0; s_pre = 0ULL; s_krem = 0u; }
    __syncthreads();
    int all = 0, done = 0;
    unsigned int krem = 0;
    unsigned long long pre = 0ULL;
    for (int pass = 0; pass < 8; pass++) {
        int shift = 56 - 8 * pass;
        if (!all) {
            sh[t] = 0u;
            __syncthreads();
            for (int i = gtid; i < n; i += gstride) {
                unsigned long long key = g_keys[i];
                if (pass > 0 && ((key ^ pre) >> (shift + 8))) continue;
                atomicAdd(&sh[(unsigned int)(key >> shift) & 255u], 1u);
            }
            __syncthreads();
            if (sh[t]) atomicAdd(&g_hist2[pass][t], sh[t]);
        }
        gsync(slot, &sc);
        unsigned int cnt = g_hist2[pass][t];
        ss[t] = cnt;
        __syncthreads();
        for (int off = 1; off < 256; off <<= 1) {
            unsigned int v = (t + off < 256) ? ss[t + off] : 0u;
            __syncthreads();
            ss[t] += v;
            __syncthreads();
        }
        if (pass == 0) {
            if (t == 0) {
                s_krem = (unsigned int)g_karr[level];
                if (ss[0] <= s_krem) { s_all = 1; s_done = 1; }
            }
            __syncthreads();
            all = s_all; done = s_done; krem = s_krem;
        }
        if (!all) {
            unsigned int kr = krem;
            if (ss[t] >= kr && (t == 255 || ss[t + 1] < kr)) {
                unsigned int above = (t < 255) ? ss[t + 1] : 0u;
                unsigned int krn = kr - above;
                s_pre = pre | ((unsigned long long)t << shift);
                s_krem = krn;
                if (cnt == krn) s_done = 1;
            }
            __syncthreads();
            pre = s_pre; krem = s_krem; done = s_done;
            __syncthreads();
        }
        if (done) break;
    }
    unsigned long long thr = pre;
    int M = (1 << sb) - 1, sbc = sb + 1;
    for (int i = gtid; i < n; i += gstride) {
        int idx = list[i];
        bool m = all || (g_keys[i] >= thr) || gt[idx];
        if (level < 2) {
            if (m) {
                int z = idx >> (2 * sb), y = (idx >> sb) & M, x = idx & M;
                int zb = z << 1, yb = y << 1, xb = x << 1;
#pragma unroll
                for (int dz = 0; dz < 2; dz++)
#pragma unroll
                    for (int dy = 0; dy < 2; dy++) {
                        int o = ((((zb + dz) << sbc) + (yb + dy)) << sbc) + xb;
                        *(unsigned short*)(occn + o) = 0x0101;
                    }
            }
        } else if (!m) {
            float4* p = (float4*)(outfeat + (size_t)idx * 16);
            float4 Z = make_float4(0.f, 0.f, 0.f, 0.f);
            p[0] = Z; p[1] = Z; p[2] = Z; p[3] = Z;
        }
    }
    if (level < 2) {
        __threadfence();  // make occ-byte stores visible before compact reads
        gsync(slot, &sc);
        compact_body(occn, nextlist, nextN, slot, &sc);
    }
}

// conv0: 32 -> 16, S=32, relu; 8 lanes/voxel; padded smem weights
__global__ __launch_bounds__(256) void k_conv0(const float* __restrict__ x,
                                               const float* __restrict__ w,
                                               const float* __restrict__ b) {
    extern __shared__ float swc[];
    for (int i = threadIdx.x; i < W0PAD; i += 256) {
        int t = i / 544, r = i % 544;
        int sub = r / 68, rr = r % 68;
        swc[i] = (rr < 64) ? w[t * 512 + sub * 64 + rr] : 0.f;
    }
    __syncthreads();
    int n = g_ncand;
    int lane = threadIdx.x & 31;
    int sub = lane & 7;
    int grp = lane >> 3;
    int gw = (blockIdx.x * blockDim.x + threadIdx.x) >> 5;
    int wstride = (gridDim.x * blockDim.x) >> 5;
    const float4 Z = make_float4(0.f, 0.f, 0.f, 0.f);
    for (int base = gw * 4; base < n; base += wstride * 4) {
        int v = base + grp;
        bool live = v < n;
        int idx = g_list0[live ? v : (n - 1)];
        int z = idx >> 10, y = (idx >> 5) & 31, xx = idx & 31;
        float4 acc[4] = {Z, Z, Z, Z};
#pragma unroll 1
        for (int t = 0; t < 27; t++) {
            int dz = t / 9 - 1, dy = (t / 3) % 3 - 1, dx = t % 3 - 1;
            int zz = z + dz, yy = y + dy, xc = xx + dx;
            if ((unsigned)zz >= 32u || (unsigned)yy >= 32u || (unsigned)xc >= 32u) continue;
            const float4* ip4 = (const float4*)(x + ((((zz << 5) + yy) << 5) + xc) * 32);
            float4 A = __ldg(ip4 + sub);
            const float4* wp4 = (const float4*)(swc + t * 544 + sub * 68);
#pragma unroll
            for (int cc = 0; cc < 4; cc++) {
                float a = comp4(A, cc);
                const float4* wr = wp4 + cc * 4;
                acc[0] = fma4(a, wr[0], acc[0]);
                acc[1] = fma4(a, wr[1], acc[1]);
                acc[2] = fma4(a, wr[2], acc[2]);
                acc[3] = fma4(a, wr[3], acc[3]);
            }
        }
        oreduce(acc[0]); oreduce(acc[1]); oreduce(acc[2]); oreduce(acc[3]);
        if (live && sub < 4) {
            float4 bb = __ldg((const float4*)b + sub);
            float4 av = acc[sub];
            float4 r = make_float4(fmaxf(av.x + bb.x, 0.f), fmaxf(av.y + bb.y, 0.f),
                                   fmaxf(av.z + bb.z, 0.f), fmaxf(av.w + bb.w, 0.f));
            ((float4*)(g_feat0 + idx * 16))[sub] = r;
        }
    }
}

// 16->16 conv3x3, relu, 1 voxel/thread, FFMA2, warp-uniform sparse TAP SKIP (bit-exact)
__global__ __launch_bounds__(256) void k_conv16(const float* __restrict__ in,
                                                const float* __restrict__ w,
                                                const float* __restrict__ b,
                                                float* __restrict__ out,
                                                const int* __restrict__ list, int S, int sb) {
    __shared__ float sw[6912];
    for (int i = threadIdx.x; i < 6912; i += blockDim.x) sw[i] = w[i];
    __syncthreads();
    int n = g_ncand;
    int lane = threadIdx.x & 31;
    int gw = (blockIdx.x * blockDim.x + threadIdx.x) >> 5;
    int wstride = (gridDim.x * blockDim.x) >> 5;
    int M = S - 1;
    const float4 Z = make_float4(0.f, 0.f, 0.f, 0.f);
    for (int base = gw * 32; base < n; base += wstride * 32) {
        int i = base + lane;
        bool live = i < n;
        int idx0 = list[live ? i : (n - 1)];
        int z0 = idx0 >> (2 * sb), y0 = (idx0 >> sb) & M, x0 = idx0 & M;
        unsigned long long acc[8];
        {
            const float2* b2 = (const float2*)b;
#pragma unroll
            for (int p = 0; p < 8; p++) {
                float2 bv = __ldg(b2 + p);
                acc[p] = pack2(bv.x, bv.y);
            }
        }
#pragma unroll 1
        for (int t = 0; t < 27; t++) {
            int dz = t / 9 - 1, dy = (t / 3) % 3 - 1, dx = t % 3 - 1;
            int za = z0 + dz, ya = y0 + dy, xa = x0 + dx;
            bool v0 = (unsigned)za < (unsigned)S && (unsigned)ya < (unsigned)S && (unsigned)xa < (unsigned)S;
            const float4* p0 = (const float4*)(in + (size_t)((((za << sb) + ya) << sb) + xa) * 16);
            float4 A0 = Z, A1 = Z, A2 = Z, A3 = Z;
            if (v0) { A0 = p0[0]; A1 = p0[1]; A2 = p0[2]; A3 = p0[3]; }
            unsigned int nzu =
                (__float_as_uint(A0.x) | __float_as_uint(A0.y) | __float_as_uint(A0.z) | __float_as_uint(A0.w)) |
                (__float_as_uint(A1.x) | __float_as_uint(A1.y) | __float_as_uint(A1.z) | __float_as_uint(A1.w)) |
                (__float_as_uint(A2.x) | __float_as_uint(A2.y) | __float_as_uint(A2.z) | __float_as_uint(A2.w)) |
                (__float_as_uint(A3.x) | __float_as_uint(A3.y) | __float_as_uint(A3.z) | __float_as_uint(A3.w));
            if (__ballot_sync(0xffffffffu, nzu != 0u) == 0u) continue;  // exact no-op skip
            const ulonglong2* wt = (const ulonglong2*)(sw + t * 256);
#pragma unroll
            for (int q = 0; q < 4; q++) {
                float4 A = (q == 0) ? A0 : ((q == 1) ? A1 : ((q == 2) ? A2 : A3));
#pragma unroll
                for (int j = 0; j < 4; j++) {
                    unsigned long long pa = pack2s(comp4(A, j));
                    const ulonglong2* wr = wt + (4 * q + j) * 4;
                    ulonglong2 w01 = wr[0], w23 = wr[1], w45 = wr[2], w67 = wr[3];
                    fma2(acc[0], pa, w01.x); fma2(acc[1], pa, w01.y);
                    fma2(acc[2], pa, w23.x); fma2(acc[3], pa, w23.y);
                    fma2(acc[4], pa, w45.x); fma2(acc[5], pa, w45.y);
                    fma2(acc[6], pa, w67.x); fma2(acc[7], pa, w67.y);
                }
            }
        }
        if (live) {
            float4* o4 = (float4*)(out + (size_t)idx0 * 16);
#pragma unroll
            for (int p = 0; p < 4; p++) {
                float2 lo = unpack2(acc[2 * p]);
                float2 hi = unpack2(acc[2 * p + 1]);
                o4[p] = make_float4(fmaxf(lo.x, 0.f), fmaxf(lo.y, 0.f),
                                    fmaxf(hi.x, 0.f), fmaxf(hi.y, 0.f));
            }
        }
    }
}

// cls conv 16->1, QUAD REMAP; zeroes g_hist2
__global__ __launch_bounds__(256) void k_cls16(const float* __restrict__ in,
                                               const float* __restrict__ w,
                                               const float* __restrict__ b,
                                               float* __restrict__ outp,
                                               const int* __restrict__ list, int S, int sb) {
    __shared__ float sw[432];
    for (int i = threadIdx.x; i < 432; i += blockDim.x) sw[i] = w[i];
    __syncthreads();
    int n = g_ncand;
    int tid = blockIdx.x * blockDim.x + threadIdx.x;
    if (tid < 2048) ((unsigned int*)g_hist2)[tid] = 0u;
    int lane = threadIdx.x & 31;
    int q = lane & 3;
    int sub = lane >> 2;
    int wgv = tid >> 5;
    int wstride = (gridDim.x * blockDim.x) >> 5;
    int M = S - 1;
    float bias = __ldg(b);
    const float4 Z = make_float4(0.f, 0.f, 0.f, 0.f);
    for (int base = wgv * 8; base < n; base += wstride * 8) {
        int i = base + sub;
        bool live = i < n;
        int idx = list[live ? i : (n - 1)];
        int z = idx >> (2 * sb), y = (idx >> sb) & M, x = idx & M;
        float acc = 0.f;
#pragma unroll 1
        for (int t = 0; t < 27; t++) {
            int dz = t / 9 - 1, dy = (t / 3) % 3 - 1, dx = t % 3 - 1;
            int zz = z + dz, yy = y + dy, xx = x + dx;
            bool v0 = (unsigned)zz < (unsigned)S && (unsigned)yy < (unsigned)S && (unsigned)xx < (unsigned)S;
            float4 A = Z;
            if (v0) A = ((const float4*)(in + (size_t)((((zz << sb) + yy) << sb) + xx) * 16))[q];
            float4 wv = ((const float4*)(sw + t * 16))[q];
            acc = fmaf(A.x, wv.x, acc); acc = fmaf(A.y, wv.y, acc);
            acc = fmaf(A.z, wv.z, acc); acc = fmaf(A.w, wv.w, acc);
        }
        acc += __shfl_xor_sync(0xffffffffu, acc, 1);
        acc += __shfl_xor_sync(0xffffffffu, acc, 2);
        acc += bias;
        if (live && q == 0) {
            outp[idx] = acc;
            g_keys[i] = make_key(acc, idx);
        }
    }
}

// conv_transpose 2x (flipped kernel), relu, FFMA2, padded oct stride
__global__ __launch_bounds__(256) void k_up(const float* __restrict__ feat,
                                            const float* __restrict__ w,
                                            const float* __restrict__ b,
                                            float* __restrict__ hout,
                                            const int* __restrict__ list, int sb) {
    __shared__ float sw[WUPAD];
    for (int i = threadIdx.x; i < WUPAD; i += blockDim.x) {
        int oct = i / 260, rr = i % 260;
        sw[i] = (rr < 256) ? w[oct * 256 + rr] : 0.f;
    }
    __syncthreads();
    int n = g_ncand;
    int sbc = sb + 1;
    int Mc = (1 << sbc) - 1;
    int stride = gridDim.x * blockDim.x;
    for (int i = blockIdx.x * blockDim.x + threadIdx.x; i < n; i += stride) {
        int cidx = list[i];
        int cz = cidx >> (2 * sbc), cy = (cidx >> sbc) & Mc, cx = cidx & Mc;
        int j = ((cz & 1) << 2) | ((cy & 1) << 1) | (cx & 1);
        int pidx = ((((cz >> 1) << sb) + (cy >> 1)) << sb) + (cx >> 1);
        const ulonglong2* wt = (const ulonglong2*)(sw + (7 - j) * 260);
        const float4* fp4 = (const float4*)(feat + (size_t)pidx * 16);
        unsigned long long acc[8];
        {
            const float2* b2 = (const float2*)b;
#pragma unroll
            for (int p = 0; p < 8; p++) {
                float2 bv = __ldg(b2 + p);
                acc[p] = pack2(bv.x, bv.y);
            }
        }
#pragma unroll
        for (int q = 0; q < 4; q++) {
            float4 A = fp4[q];
#pragma unroll
            for (int jj = 0; jj < 4; jj++) {
                unsigned long long pa = pack2s(comp4(A, jj));
                const ulonglong2* wr = wt + (4 * q + jj) * 4;
                ulonglong2 w01 = wr[0], w23 = wr[1], w45 = wr[2], w67 = wr[3];
                fma2(acc[0], pa, w01.x); fma2(acc[1], pa, w01.y);
                fma2(acc[2], pa, w23.x); fma2(acc[3], pa, w23.y);
                fma2(acc[4], pa, w45.x); fma2(acc[5], pa, w45.y);
                fma2(acc[6], pa, w67.x); fma2(acc[7], pa, w67.y);
            }
        }
        float4* op = (float4*)(hout + (size_t)cidx * 16);
#pragma unroll
        for (int p = 0; p < 4; p++) {
            float2 lo = unpack2(acc[2 * p]);
            float2 hi = unpack2(acc[2 * p + 1]);
            op[p] = make_float4(fmaxf(lo.x, 0.f), fmaxf(lo.y, 0.f),
                                fmaxf(hi.x, 0.f), fmaxf(hi.y, 0.f));
        }
    }
}

extern "C" void kernel_launch(void* const* d_in, const int* in_sizes, int n_in,
                              void* d_out, int out_size) {
    const float* x   = (const float*)d_in[0];
    const void* occ0 = d_in[1];
    const void* gt0  = d_in[2];
    const void* gt1  = d_in[3];
    const void* gt2  = d_in[4];
    const float* wc0 = (const float*)d_in[5],  *bc0 = (const float*)d_in[6];
    const float* wk0 = (const float*)d_in[7],  *bk0 = (const float*)d_in[8];
    const float* wu1 = (const float*)d_in[9],  *bu1 = (const float*)d_in[10];
    const float* wc1 = (const float*)d_in[11], *bc1 = (const float*)d_in[12];
    const float* wk1 = (const float*)d_in[13], *bk1 = (const float*)d_in[14];
    const float* wu2 = (const float*)d_in[15], *bu2 = (const float*)d_in[16];
    const float* wc2 = (const float*)d_in[17], *bc2 = (const float*)d_in[18];
    const float* wk2 = (const float*)d_in[19], *bk2 = (const float*)d_in[20];
    const int* n0 = (const int*)d_in[21];
    const int* n1 = (const int*)d_in[22];
    const int* n2 = (const int*)d_in[23];
    float* out = (float*)d_out;

    int *dlist0, *dlist1, *dlist2;
    cudaGetSymbolAddress((void**)&dlist0, g_list0);
    cudaGetSymbolAddress((void**)&dlist1, g_list1);
    cudaGetSymbolAddress((void**)&dlist2, g_list2);
    float *dh1, *dh2, *df0, *df1;
    cudaGetSymbolAddress((void**)&dh1, g_h1);
    cudaGetSymbolAddress((void**)&dh2, g_h2);
    cudaGetSymbolAddress((void**)&df0, g_feat0);
    cudaGetSymbolAddress((void**)&df1, g_feat1);
    unsigned char *dg0, *dg1, *dg2, *do0, *do1, *do2;
    cudaGetSymbolAddress((void**)&dg0, g_gt0);
    cudaGetSymbolAddress((void**)&dg1, g_gt1);
    cudaGetSymbolAddress((void**)&dg2, g_gt2);
    cudaGetSymbolAddress((void**)&do0, g_occ0);
    cudaGetSymbolAddress((void**)&do1, g_occ1);
    cudaGetSymbolAddress((void**)&do2, g_occ2);

    static int smem_set = 0;
    if (!smem_set) {
        cudaFuncSetAttribute(k_conv0, cudaFuncAttributeMaxDynamicSharedMemorySize,
                             W0PAD * (int)sizeof(float));
        smem_set = 1;
    }

    k_detect<<<1, 256>>>((const unsigned char*)occ0, n0, n1, n2);            // 0
    k_zero_cvt<<<2048, 256>>>((float4*)out, occ0, gt0, gt1, gt2);            // 1
    k_compact<<<GSB, GST>>>(do0, dlist0, V0, 0);                             // 2
    k_conv0<<<444, 256, W0PAD * sizeof(float)>>>(x, wc0, bc0);               // 3 <- profiled
    k_cls16<<<592, 256>>>(df0, wk0, bk0, out, dlist0, 32, 5);
    k_selcomp<<<GSB, GST>>>(dlist0, dg0, nullptr, do1, dlist1, 0, 5, V1, 1);

    // ---- level 1 ----
    k_up<<<1024, 256>>>(df0, wu1, bu1, dh1, dlist1, 5);
    k_conv16<<<1024, 256>>>(dh1, wc1, bc1, df1, dlist1, 64, 6);
    k_cls16<<<1024, 256>>>(df1, wk1, bk1, out + OFF_CLS1, dlist1, 64, 6);
    k_selcomp<<<GSB, GST>>>(dlist1, dg1, nullptr, do2, dlist2, 1, 6, V2, 3);

    // ---- level 2 ----
    k_up<<<2048, 256>>>(df1, wu2, bu2, dh2, dlist2, 6);
    k_conv16<<<2048, 256>>>(dh2, wc2, bc2, out + OFF_OUT, dlist2, 128, 7);
    k_cls16<<<2048, 256>>>(out + OFF_OUT, wk2, bk2, out + OFF_CLS2, dlist2, 128, 7);
    k_selcomp<<<GSB, GST>>>(dlist2, dg2, out + OFF_OUT, nullptr, nullptr, 2, 7, 0, 5);
}